// round 3
// baseline (speedup 1.0000x reference)
#include <cuda_runtime.h>
#include <math.h>

#define B_BATCH 128
#define D_DIM   2048
#define P_DIM   16000
#define THREADS 1024

static __device__ int   g_idx[2 * D_DIM];
static __device__ float g_sgn[2 * D_DIM];

// ---------------------------------------------------------------------------
// Kernel 1: recover the sparse count-sketch (one +/-1 per row) from dense C.
// One block per row, chunked scan with early exit: expected ~53% of the
// 256MB read instead of 100%.
// ---------------------------------------------------------------------------
#define EX_THREADS 256
#define EX_CHUNK   (EX_THREADS)            // float4s per chunk = 4KB
#define EX_NF4     (P_DIM / 4)             // 4000 float4 per row

__global__ void __launch_bounds__(EX_THREADS)
extract_kernel(const float* __restrict__ C1, const float* __restrict__ C2) {
    __shared__ int found;
    int row = blockIdx.x;  // 0..4095: first 2048 -> C1, rest -> C2
    const float* base = (row < D_DIM) ? (C1 + (size_t)row * P_DIM)
                                      : (C2 + (size_t)(row - D_DIM) * P_DIM);
    const float4* b4 = (const float4*)base;
    if (threadIdx.x == 0) found = 0;
    __syncthreads();

    for (int start = 0; start < EX_NF4; start += EX_CHUNK) {
        int i = start + threadIdx.x;
        if (i < EX_NF4) {
            float4 v = b4[i];
            if (v.x != 0.0f || v.y != 0.0f || v.z != 0.0f || v.w != 0.0f) {
                int   idx;
                float sgn;
                if      (v.x != 0.0f) { idx = 4 * i + 0; sgn = v.x; }
                else if (v.y != 0.0f) { idx = 4 * i + 1; sgn = v.y; }
                else if (v.z != 0.0f) { idx = 4 * i + 2; sgn = v.z; }
                else                  { idx = 4 * i + 3; sgn = v.w; }
                g_idx[row] = idx;
                g_sgn[row] = sgn;
                found = 1;
            }
        }
        __syncthreads();
        if (found) break;
        __syncthreads();
    }
}

// base-5 digit reversal of 3 digits (involution), x in [0,125)
__device__ __forceinline__ int dr5(int x) {
    int a = x / 25;
    int rem = x - 25 * a;
    int b = rem / 5;
    int c = rem - 5 * b;
    return c * 25 + b * 5 + a;
}

// complex helpers
__device__ __forceinline__ void cmul(float& ar, float& ai, float br, float bi) {
    float tr = ar * br - ai * bi;
    ai = ar * bi + ai * br;
    ar = tr;
}
__device__ __forceinline__ void cmulc(float& ar, float& ai, float br, float bi) {
    // multiply by conj(b)
    float tr = ar * br + ai * bi;
    ai = ai * br - ar * bi;
    ar = tr;
}

// Radix-8 DIT (3 merged radix-2 DIT stages).
__device__ __forceinline__ void radix8_dit(float xr[8], float xi[8], int j,
                                           const float* t128r, const float* t128i) {
    float war = t128r[8 * j], wai = t128i[8 * j];
#pragma unroll
    for (int t = 0; t < 8; t += 2) {
        float vr = xr[t + 1], vi = xi[t + 1];
        cmul(vr, vi, war, wai);
        xr[t + 1] = xr[t] - vr; xi[t + 1] = xi[t] - vi;
        xr[t] += vr;            xi[t] += vi;
    }
    float wb0r = t128r[4 * j], wb0i = t128i[4 * j];
    float wb1r = t128r[4 * j + 32], wb1i = t128i[4 * j + 32];
#pragma unroll
    for (int q = 0; q < 2; q++) {
        int b0 = 4 * q;
        {
            float vr = xr[b0 + 2], vi = xi[b0 + 2];
            cmul(vr, vi, wb0r, wb0i);
            xr[b0 + 2] = xr[b0] - vr; xi[b0 + 2] = xi[b0] - vi;
            xr[b0] += vr;             xi[b0] += vi;
        }
        {
            float vr = xr[b0 + 3], vi = xi[b0 + 3];
            cmul(vr, vi, wb1r, wb1i);
            xr[b0 + 3] = xr[b0 + 1] - vr; xi[b0 + 3] = xi[b0 + 1] - vi;
            xr[b0 + 1] += vr;             xi[b0 + 1] += vi;
        }
    }
#pragma unroll
    for (int t = 0; t < 4; t++) {
        float wr = t128r[2 * j + 16 * t], wi = t128i[2 * j + 16 * t];
        float vr = xr[t + 4], vi = xi[t + 4];
        cmul(vr, vi, wr, wi);
        xr[t + 4] = xr[t] - vr; xi[t + 4] = xi[t] - vi;
        xr[t] += vr;            xi[t] += vi;
    }
}

// Radix-8 DIF (3 merged radix-2 DIF stages, inverse direction = conj twiddles).
__device__ __forceinline__ void radix8_dif(float xr[8], float xi[8], int j,
                                           const float* t128r, const float* t128i) {
#pragma unroll
    for (int t = 0; t < 4; t++) {
        float wr = t128r[2 * j + 16 * t], wi = t128i[2 * j + 16 * t];
        float ur = xr[t], ui = xi[t];
        float vr = xr[t + 4], vi = xi[t + 4];
        xr[t] = ur + vr; xi[t] = ui + vi;
        float dr_ = ur - vr, di_ = ui - vi;
        cmulc(dr_, di_, wr, wi);
        xr[t + 4] = dr_; xi[t + 4] = di_;
    }
    float wb0r = t128r[4 * j], wb0i = t128i[4 * j];
    float wb1r = t128r[4 * j + 32], wb1i = t128i[4 * j + 32];
#pragma unroll
    for (int q = 0; q < 2; q++) {
        int b0 = 4 * q;
        {
            float ur = xr[b0], ui = xi[b0];
            float vr = xr[b0 + 2], vi = xi[b0 + 2];
            xr[b0] = ur + vr; xi[b0] = ui + vi;
            float dr_ = ur - vr, di_ = ui - vi;
            cmulc(dr_, di_, wb0r, wb0i);
            xr[b0 + 2] = dr_; xi[b0 + 2] = di_;
        }
        {
            float ur = xr[b0 + 1], ui = xi[b0 + 1];
            float vr = xr[b0 + 3], vi = xi[b0 + 3];
            xr[b0 + 1] = ur + vr; xi[b0 + 1] = ui + vi;
            float dr_ = ur - vr, di_ = ui - vi;
            cmulc(dr_, di_, wb1r, wb1i);
            xr[b0 + 3] = dr_; xi[b0 + 3] = di_;
        }
    }
    float war = t128r[8 * j], wai = t128i[8 * j];
#pragma unroll
    for (int t = 0; t < 8; t += 2) {
        float ur = xr[t], ui = xi[t];
        float vr = xr[t + 1], vi = xi[t + 1];
        xr[t] = ur + vr; xi[t] = ui + vi;
        float dr_ = ur - vr, di_ = ui - vi;
        cmulc(dr_, di_, war, wai);
        xr[t + 1] = dr_; xi[t + 1] = di_;
    }
}

// ---------------------------------------------------------------------------
// Kernel 2: z = y1 + i*y2, Z = FFT_16000 (128x125 four-step), Hermitian split
// + pointwise multiply, phi = Re(IFFT)/N.  All in shared memory, 1 CTA/row.
// ---------------------------------------------------------------------------
__global__ void __launch_bounds__(THREADS)
mcb_fft_kernel(const float* __restrict__ x1, const float* __restrict__ x2,
               float* __restrict__ out) {
    extern __shared__ float sm[];
    float* SR = sm;            // 16000 floats
    float* SI = sm + P_DIM;    // 16000 floats
    __shared__ float t128r[128], t128i[128];   // e^{-2pi i t/128}
    __shared__ float t125r[125], t125i[125];   // e^{-2pi i t/125}
    __shared__ float tSr[125],  tSi[125];      // e^{-2pi i t/16000}

    const int tid = threadIdx.x;
    const int b   = blockIdx.x;
    const double TWO_PI = 6.283185307179586476925286766559;

    for (int t = tid; t < 128; t += THREADS) {
        double s, c; sincos(-TWO_PI * (double)t / 128.0, &s, &c);
        t128r[t] = (float)c; t128i[t] = (float)s;
    }
    for (int t = tid; t < 125; t += THREADS) {
        double s, c;
        sincos(-TWO_PI * (double)t / 125.0, &s, &c);
        t125r[t] = (float)c; t125i[t] = (float)s;
        sincos(-TWO_PI * (double)t / 16000.0, &s, &c);
        tSr[t] = (float)c; tSi[t] = (float)s;
    }
    for (int i = tid; i < P_DIM; i += THREADS) { SR[i] = 0.0f; SI[i] = 0.0f; }
    __syncthreads();

    // scatter: y1 -> real, y2 -> imag, rows bit-reversed for the DIT stages
    for (int d = tid; d < D_DIM; d += THREADS) {
        int p = g_idx[d];
        float v = x1[b * D_DIM + d] * g_sgn[d];
        int n1 = p / 125, n2 = p - n1 * 125;
        int r = __brev(n1) >> 25;
        atomicAdd(&SR[r * 125 + n2], v);
        p = g_idx[D_DIM + d];
        v = x2[b * D_DIM + d] * g_sgn[D_DIM + d];
        n1 = p / 125; n2 = p - n1 * 125;
        r = __brev(n1) >> 25;
        atomicAdd(&SI[r * 125 + n2], v);
    }
    __syncthreads();

    // ---- forward radix-2 stages 0..2 merged (rows 8g+t, fixed col) ----
    for (int idx = tid; idx < 2000; idx += THREADS) {
        int c = idx % 125;
        int g = idx / 125;
        int base = g * 1000 + c;
        float xr[8], xi[8];
#pragma unroll
        for (int t = 0; t < 8; t++) { xr[t] = SR[base + t * 125]; xi[t] = SI[base + t * 125]; }
        radix8_dit(xr, xi, 0, t128r, t128i);
#pragma unroll
        for (int t = 0; t < 8; t++) { SR[base + t * 125] = xr[t]; SI[base + t * 125] = xi[t]; }
    }
    __syncthreads();

    // ---- forward radix-2 stages 3..5 merged (rows 64u + j + 8t) ----
    for (int idx = tid; idx < 2000; idx += THREADS) {
        int c = idx % 125;
        int g = idx / 125;          // 0..15
        int u = g >> 3, j = g & 7;
        int base = (u * 64 + j) * 125 + c;
        float xr[8], xi[8];
#pragma unroll
        for (int t = 0; t < 8; t++) { xr[t] = SR[base + t * 1000]; xi[t] = SI[base + t * 1000]; }
        radix8_dit(xr, xi, j, t128r, t128i);
#pragma unroll
        for (int t = 0; t < 8; t++) { SR[base + t * 1000] = xr[t]; SI[base + t * 1000] = xi[t]; }
    }
    __syncthreads();

    // ---- forward stage 6 (radix-2) fused with inter-phase twiddle ----
    for (int idx = tid; idx < 8000; idx += THREADS) {
        int c = idx % 125;
        int r = idx / 125;          // 0..63
        int p0 = r * 125 + c;
        int p1 = p0 + 8000;
        float ur = SR[p0], ui = SI[p0];
        float vr = SR[p1], vi = SI[p1];
        cmul(vr, vi, t128r[r], t128i[r]);
        float X0r = ur + vr, X0i = ui + vi;
        float X1r = ur - vr, X1i = ui - vi;
        int mm = c * r;
        int q = mm / 125, rr = mm - q * 125;
        float wr = t128r[q], wi = t128i[q];
        cmul(wr, wi, tSr[rr], tSi[rr]);
        cmul(X0r, X0i, wr, wi);
        SR[p0] = X0r; SI[p0] = X0i;
        int mm2 = mm + 64 * c;
        q = mm2 / 125; rr = mm2 - q * 125;
        wr = t128r[q]; wi = t128i[q];
        cmul(wr, wi, tSr[rr], tSi[rr]);
        cmul(X1r, X1i, wr, wi);
        SR[p1] = X1r; SI[p1] = X1i;
    }
    __syncthreads();

    // ---- forward: 3 radix-5 DIF stages (length-125 row FFTs) ----
    const float C72  =  0.30901699437494742f, S72  = 0.95105651629515357f;
    const float C144 = -0.80901699437494745f, S144 = 0.58778525229247314f;
#pragma unroll
    for (int sidx = 0; sidx < 3; sidx++) {
        const int L = (sidx == 0) ? 125 : (sidx == 1) ? 25 : 5;
        const int m = L / 5;
        const int f = 125 / L;
        for (int idx = tid; idx < 3200; idx += THREADS) {
            int r  = idx & 127;
            int bj = idx >> 7;
            int j  = bj % m;
            int base = r * 125 + (bj / m) * L + j;
            float a0r = SR[base],         a0i = SI[base];
            float a1r = SR[base + m],     a1i = SI[base + m];
            float a2r = SR[base + 2 * m], a2i = SI[base + 2 * m];
            float a3r = SR[base + 3 * m], a3i = SI[base + 3 * m];
            float a4r = SR[base + 4 * m], a4i = SI[base + 4 * m];
            float t1r = a1r + a4r, t1i = a1i + a4i;
            float t3r = a1r - a4r, t3i = a1i - a4i;
            float t2r = a2r + a3r, t2i = a2i + a3i;
            float t4r = a2r - a3r, t4i = a2i - a3i;
            float y0r = a0r + t1r + t2r, y0i = a0i + t1i + t2i;
            float m1r = a0r + C72 * t1r + C144 * t2r;
            float m1i = a0i + C72 * t1i + C144 * t2i;
            float m2r = a0r + C144 * t1r + C72 * t2r;
            float m2i = a0i + C144 * t1i + C72 * t2i;
            float v1r = S72 * t3r + S144 * t4r, v1i = S72 * t3i + S144 * t4i;
            float v2r = S144 * t3r - S72 * t4r, v2i = S144 * t3i - S72 * t4i;
            float y1r = m1r + v1i, y1i = m1i - v1r;
            float y2r = m2r + v2i, y2i = m2i - v2r;
            float y3r = m2r - v2i, y3i = m2i + v2r;
            float y4r = m1r - v1i, y4i = m1i + v1r;
            int jf = j * f;
            float wr, wi;
            SR[base] = y0r; SI[base] = y0i;
            wr = t125r[jf];     wi = t125i[jf];
            SR[base + m]     = y1r * wr - y1i * wi; SI[base + m]     = y1r * wi + y1i * wr;
            wr = t125r[2 * jf]; wi = t125i[2 * jf];
            SR[base + 2 * m] = y2r * wr - y2i * wi; SI[base + 2 * m] = y2r * wi + y2i * wr;
            wr = t125r[3 * jf]; wi = t125i[3 * jf];
            SR[base + 3 * m] = y3r * wr - y3i * wi; SI[base + 3 * m] = y3r * wi + y3i * wr;
            wr = t125r[4 * jf]; wi = t125i[4 * jf];
            SR[base + 4 * m] = y4r * wr - y4i * wi; SI[base + 4 * m] = y4r * wi + y4i * wr;
        }
        __syncthreads();
    }

    // ---- Hermitian split + pointwise multiply, in scrambled storage ----
    for (int k = tid; k <= 8000; k += THREADS) {
        if (k == 0) {
            float zr = SR[0], zi = SI[0];
            SR[0] = zr * zi; SI[0] = 0.0f;
        } else if (k == 8000) {
            const int addr = 64 * 125 + 62;
            float zr = SR[addr], zi = SI[addr];
            SR[addr] = zr * zi; SI[addr] = 0.0f;
        } else {
            int k1 = k & 127, k2 = k >> 7;
            int pa = k1 * 125 + dr5(k2);
            int kp = P_DIM - k;
            int k1p = kp & 127, k2p = kp >> 7;
            int pb = k1p * 125 + dr5(k2p);
            float Ar = SR[pa], Ai = SI[pa];
            float Br = SR[pb], Bi = SI[pb];
            float F1r = 0.5f * (Ar + Br), F1i = 0.5f * (Ai - Bi);
            float F2r = 0.5f * (Ai + Bi), F2i = 0.5f * (Br - Ar);
            float Hr = F1r * F2r - F1i * F2i;
            float Hi = F1r * F2i + F1i * F2r;
            SR[pa] = Hr; SI[pa] = Hi;
            SR[pb] = Hr; SI[pb] = -Hi;
        }
    }
    __syncthreads();

    // ---- inverse: 3 radix-5 DIT stages (rows), conj twiddles ----
#pragma unroll
    for (int sidx = 0; sidx < 3; sidx++) {
        const int L = (sidx == 0) ? 5 : (sidx == 1) ? 25 : 125;
        const int m = L / 5;
        const int f = 125 / L;
        for (int idx = tid; idx < 3200; idx += THREADS) {
            int r  = idx & 127;
            int bj = idx >> 7;
            int j  = bj % m;
            int base = r * 125 + (bj / m) * L + j;
            int jf = j * f;
            float wr, wi, xr, xi;
            float a0r = SR[base], a0i = SI[base];
            xr = SR[base + m];     xi = SI[base + m];
            wr = t125r[jf];     wi = -t125i[jf];
            float a1r = xr * wr - xi * wi, a1i = xr * wi + xi * wr;
            xr = SR[base + 2 * m]; xi = SI[base + 2 * m];
            wr = t125r[2 * jf]; wi = -t125i[2 * jf];
            float a2r = xr * wr - xi * wi, a2i = xr * wi + xi * wr;
            xr = SR[base + 3 * m]; xi = SI[base + 3 * m];
            wr = t125r[3 * jf]; wi = -t125i[3 * jf];
            float a3r = xr * wr - xi * wi, a3i = xr * wi + xi * wr;
            xr = SR[base + 4 * m]; xi = SI[base + 4 * m];
            wr = t125r[4 * jf]; wi = -t125i[4 * jf];
            float a4r = xr * wr - xi * wi, a4i = xr * wi + xi * wr;
            float t1r = a1r + a4r, t1i = a1i + a4i;
            float t3r = a1r - a4r, t3i = a1i - a4i;
            float t2r = a2r + a3r, t2i = a2i + a3i;
            float t4r = a2r - a3r, t4i = a2i - a3i;
            float y0r = a0r + t1r + t2r, y0i = a0i + t1i + t2i;
            float m1r = a0r + C72 * t1r + C144 * t2r;
            float m1i = a0i + C72 * t1i + C144 * t2i;
            float m2r = a0r + C144 * t1r + C72 * t2r;
            float m2i = a0i + C144 * t1i + C72 * t2i;
            float v1r = S72 * t3r + S144 * t4r, v1i = S72 * t3i + S144 * t4i;
            float v2r = S144 * t3r - S72 * t4r, v2i = S144 * t3i - S72 * t4i;
            SR[base]         = y0r;        SI[base]         = y0i;
            SR[base + m]     = m1r - v1i;  SI[base + m]     = m1i + v1r;
            SR[base + 2 * m] = m2r - v2i;  SI[base + 2 * m] = m2i + v2r;
            SR[base + 3 * m] = m2r + v2i;  SI[base + 3 * m] = m2i - v2r;
            SR[base + 4 * m] = m1r + v1i;  SI[base + 4 * m] = m1i - v1r;
        }
        __syncthreads();
    }

    // ---- inverse inter-phase twiddle (conj) fused with radix-2 stage 6 ----
    for (int idx = tid; idx < 8000; idx += THREADS) {
        int c = idx % 125;
        int r = idx / 125;
        int p0 = r * 125 + c;
        int p1 = p0 + 8000;
        float ur = SR[p0], ui = SI[p0];
        float vr = SR[p1], vi = SI[p1];
        int mm = c * r;
        int q = mm / 125, rr = mm - q * 125;
        float wr = t128r[q], wi = t128i[q];
        cmul(wr, wi, tSr[rr], tSi[rr]);
        cmulc(ur, ui, wr, wi);
        int mm2 = mm + 64 * c;
        q = mm2 / 125; rr = mm2 - q * 125;
        wr = t128r[q]; wi = t128i[q];
        cmul(wr, wi, tSr[rr], tSi[rr]);
        cmulc(vr, vi, wr, wi);
        SR[p0] = ur + vr; SI[p0] = ui + vi;
        float dr_ = ur - vr, di_ = ui - vi;
        cmulc(dr_, di_, t128r[r], t128i[r]);
        SR[p1] = dr_; SI[p1] = di_;
    }
    __syncthreads();

    // ---- inverse radix-2 stages 5..3 merged ----
    for (int idx = tid; idx < 2000; idx += THREADS) {
        int c = idx % 125;
        int g = idx / 125;
        int u = g >> 3, j = g & 7;
        int base = (u * 64 + j) * 125 + c;
        float xr[8], xi[8];
#pragma unroll
        for (int t = 0; t < 8; t++) { xr[t] = SR[base + t * 1000]; xi[t] = SI[base + t * 1000]; }
        radix8_dif(xr, xi, j, t128r, t128i);
#pragma unroll
        for (int t = 0; t < 8; t++) { SR[base + t * 1000] = xr[t]; SI[base + t * 1000] = xi[t]; }
    }
    __syncthreads();

    // ---- inverse radix-2 stages 2..0 merged ----
    for (int idx = tid; idx < 2000; idx += THREADS) {
        int c = idx % 125;
        int g = idx / 125;
        int base = g * 1000 + c;
        float xr[8], xi[8];
#pragma unroll
        for (int t = 0; t < 8; t++) { xr[t] = SR[base + t * 125]; xi[t] = SI[base + t * 125]; }
        radix8_dif(xr, xi, 0, t128r, t128i);
#pragma unroll
        for (int t = 0; t < 8; t++) { SR[base + t * 125] = xr[t]; SI[base + t * 125] = xi[t]; }
    }
    __syncthreads();

    // ---- write real part, un-permuting rows, with 1/N ----
    const float scale = 1.0f / 16000.0f;
    for (int n = tid; n < P_DIM; n += THREADS) {
        int n1 = n / 125, n2 = n - n1 * 125;
        int r = __brev(n1) >> 25;
        out[b * P_DIM + n] = SR[r * 125 + n2] * scale;
    }
}

extern "C" void kernel_launch(void* const* d_in, const int* in_sizes, int n_in,
                              void* d_out, int out_size) {
    const float* x1 = (const float*)d_in[0];
    const float* x2 = (const float*)d_in[1];
    const float* C1 = (const float*)d_in[2];
    const float* C2 = (const float*)d_in[3];
    float* out = (float*)d_out;

    extract_kernel<<<2 * D_DIM, EX_THREADS>>>(C1, C2);

    const size_t smem = (size_t)2 * P_DIM * sizeof(float);  // 128000 B
    cudaFuncSetAttribute(mcb_fft_kernel,
                         cudaFuncAttributeMaxDynamicSharedMemorySize, (int)smem);
    mcb_fft_kernel<<<B_BATCH, THREADS, smem>>>(x1, x2, out);
}

// round 4
// speedup vs baseline: 1.1867x; 1.1867x over previous
#include <cuda_runtime.h>
#include <math.h>

#define B_BATCH 128
#define D_DIM   2048
#define P_DIM   16000
#define THREADS 1024

static __device__ int   g_idx[2 * D_DIM];
static __device__ float g_sgn[2 * D_DIM];

// ---------------------------------------------------------------------------
// Kernel 1: recover the sparse count-sketch (one +/-1 per row) from dense C.
// Flat grid-stride full scan: perfectly coalesced, high MLP, row math only
// on the 4096 hit paths.
// ---------------------------------------------------------------------------
#define EX_BLOCKS  2048
#define EX_THREADS 256

__global__ void __launch_bounds__(EX_THREADS)
extract_kernel(const float* __restrict__ C1, const float* __restrict__ C2) {
    const int nf4 = D_DIM * (P_DIM / 4);   // 8,192,000 float4 per matrix
    const int stride = gridDim.x * blockDim.x;
    const int t0 = blockIdx.x * blockDim.x + threadIdx.x;
#pragma unroll
    for (int m = 0; m < 2; m++) {
        const float4* A = (const float4*)(m == 0 ? C1 : C2);
        for (int i = t0; i < nf4; i += stride) {
            float4 v = A[i];
            if (v.x != 0.0f || v.y != 0.0f || v.z != 0.0f || v.w != 0.0f) {
                int row  = i / (P_DIM / 4);
                int c4   = 4 * (i - row * (P_DIM / 4));
                int   idx;
                float sgn;
                if      (v.x != 0.0f) { idx = c4 + 0; sgn = v.x; }
                else if (v.y != 0.0f) { idx = c4 + 1; sgn = v.y; }
                else if (v.z != 0.0f) { idx = c4 + 2; sgn = v.z; }
                else                  { idx = c4 + 3; sgn = v.w; }
                g_idx[m * D_DIM + row] = idx;
                g_sgn[m * D_DIM + row] = sgn;
            }
        }
    }
}

// base-5 digit reversal of 3 digits (involution), x in [0,125)
__device__ __forceinline__ int dr5(int x) {
    int a = x / 25;
    int rem = x - 25 * a;
    int b = rem / 5;
    int c = rem - 5 * b;
    return c * 25 + b * 5 + a;
}

typedef float2 cplx;
__device__ __forceinline__ cplx cmul(cplx a, cplx b) {
    return make_float2(a.x * b.x - a.y * b.y, a.x * b.y + a.y * b.x);
}
__device__ __forceinline__ cplx cmulc(cplx a, cplx b) {   // a * conj(b)
    return make_float2(a.x * b.x + a.y * b.y, a.y * b.x - a.x * b.y);
}
__device__ __forceinline__ cplx cadd(cplx a, cplx b) { return make_float2(a.x + b.x, a.y + b.y); }
__device__ __forceinline__ cplx csub(cplx a, cplx b) { return make_float2(a.x - b.x, a.y - b.y); }

// Radix-8 DIT (3 merged radix-2 DIT stages).
__device__ __forceinline__ void radix8_dit(cplx x[8], int j, const cplx* t128) {
    cplx wa = t128[8 * j];
#pragma unroll
    for (int t = 0; t < 8; t += 2) {
        cplx v = cmul(x[t + 1], wa);
        x[t + 1] = csub(x[t], v);
        x[t]     = cadd(x[t], v);
    }
    cplx wb0 = t128[4 * j];
    cplx wb1 = t128[4 * j + 32];
#pragma unroll
    for (int q = 0; q < 2; q++) {
        int b0 = 4 * q;
        {
            cplx v = cmul(x[b0 + 2], wb0);
            x[b0 + 2] = csub(x[b0], v);
            x[b0]     = cadd(x[b0], v);
        }
        {
            cplx v = cmul(x[b0 + 3], wb1);
            x[b0 + 3] = csub(x[b0 + 1], v);
            x[b0 + 1] = cadd(x[b0 + 1], v);
        }
    }
#pragma unroll
    for (int t = 0; t < 4; t++) {
        cplx w = t128[2 * j + 16 * t];
        cplx v = cmul(x[t + 4], w);
        x[t + 4] = csub(x[t], v);
        x[t]     = cadd(x[t], v);
    }
}

// Radix-8 DIF (3 merged radix-2 DIF stages, inverse direction = conj twiddles).
__device__ __forceinline__ void radix8_dif(cplx x[8], int j, const cplx* t128) {
#pragma unroll
    for (int t = 0; t < 4; t++) {
        cplx w = t128[2 * j + 16 * t];
        cplx u = x[t], v = x[t + 4];
        x[t]     = cadd(u, v);
        x[t + 4] = cmulc(csub(u, v), w);
    }
    cplx wb0 = t128[4 * j];
    cplx wb1 = t128[4 * j + 32];
#pragma unroll
    for (int q = 0; q < 2; q++) {
        int b0 = 4 * q;
        {
            cplx u = x[b0], v = x[b0 + 2];
            x[b0]     = cadd(u, v);
            x[b0 + 2] = cmulc(csub(u, v), wb0);
        }
        {
            cplx u = x[b0 + 1], v = x[b0 + 3];
            x[b0 + 1] = cadd(u, v);
            x[b0 + 3] = cmulc(csub(u, v), wb1);
        }
    }
    cplx wa = t128[8 * j];
#pragma unroll
    for (int t = 0; t < 8; t += 2) {
        cplx u = x[t], v = x[t + 1];
        x[t]     = cadd(u, v);
        x[t + 1] = cmulc(csub(u, v), wa);
    }
}

// ---------------------------------------------------------------------------
// Kernel 2: z = y1 + i*y2, Z = FFT_16000 (128x125 four-step), Hermitian split
// + pointwise multiply, phi = Re(IFFT)/N.  float2 interleaved shared storage.
// ---------------------------------------------------------------------------
__global__ void __launch_bounds__(THREADS)
mcb_fft_kernel(const float* __restrict__ x1, const float* __restrict__ x2,
               float* __restrict__ out) {
    extern __shared__ cplx S[];                // 16000 complex = 128000 B
    __shared__ cplx t128[128];                 // e^{-2pi i t/128}
    __shared__ cplx t125[125];                 // e^{-2pi i t/125}
    __shared__ cplx tS[125];                   // e^{-2pi i t/16000}

    const int tid = threadIdx.x;
    const int b   = blockIdx.x;
    const double TWO_PI = 6.283185307179586476925286766559;

    for (int t = tid; t < 128; t += THREADS) {
        double s, c; sincos(-TWO_PI * (double)t / 128.0, &s, &c);
        t128[t] = make_float2((float)c, (float)s);
    }
    for (int t = tid; t < 125; t += THREADS) {
        double s, c;
        sincos(-TWO_PI * (double)t / 125.0, &s, &c);
        t125[t] = make_float2((float)c, (float)s);
        sincos(-TWO_PI * (double)t / 16000.0, &s, &c);
        tS[t] = make_float2((float)c, (float)s);
    }
    for (int i = tid; i < P_DIM; i += THREADS) S[i] = make_float2(0.0f, 0.0f);
    __syncthreads();

    // scatter: y1 -> real, y2 -> imag, rows bit-reversed for the DIT stages
    for (int d = tid; d < D_DIM; d += THREADS) {
        int p = g_idx[d];
        float v = x1[b * D_DIM + d] * g_sgn[d];
        int n1 = p / 125, n2 = p - n1 * 125;
        int r = __brev(n1) >> 25;
        atomicAdd(&S[r * 125 + n2].x, v);
        p = g_idx[D_DIM + d];
        v = x2[b * D_DIM + d] * g_sgn[D_DIM + d];
        n1 = p / 125; n2 = p - n1 * 125;
        r = __brev(n1) >> 25;
        atomicAdd(&S[r * 125 + n2].y, v);
    }
    __syncthreads();

    // ---- forward radix-2 stages 0..2 merged (rows 8g+t, fixed col) ----
    for (int idx = tid; idx < 2000; idx += THREADS) {
        int c = idx % 125;
        int g = idx / 125;
        int base = g * 1000 + c;
        cplx x[8];
#pragma unroll
        for (int t = 0; t < 8; t++) x[t] = S[base + t * 125];
        radix8_dit(x, 0, t128);
#pragma unroll
        for (int t = 0; t < 8; t++) S[base + t * 125] = x[t];
    }
    __syncthreads();

    // ---- forward radix-2 stages 3..5 merged (rows 64u + j + 8t) ----
    for (int idx = tid; idx < 2000; idx += THREADS) {
        int c = idx % 125;
        int g = idx / 125;          // 0..15
        int u = g >> 3, j = g & 7;
        int base = (u * 64 + j) * 125 + c;
        cplx x[8];
#pragma unroll
        for (int t = 0; t < 8; t++) x[t] = S[base + t * 1000];
        radix8_dit(x, j, t128);
#pragma unroll
        for (int t = 0; t < 8; t++) S[base + t * 1000] = x[t];
    }
    __syncthreads();

    // ---- forward stage 6 (radix-2) fused with inter-phase twiddle ----
    for (int idx = tid; idx < 8000; idx += THREADS) {
        int c = idx % 125;
        int r = idx / 125;          // 0..63
        int p0 = r * 125 + c;
        int p1 = p0 + 8000;
        cplx u = S[p0];
        cplx v = cmul(S[p1], t128[r]);
        cplx X0 = cadd(u, v);
        cplx X1 = csub(u, v);
        int mm = c * r;
        int q = mm / 125, rr = mm - q * 125;
        S[p0] = cmul(X0, cmul(t128[q], tS[rr]));
        int mm2 = mm + 64 * c;
        q = mm2 / 125; rr = mm2 - q * 125;
        S[p1] = cmul(X1, cmul(t128[q], tS[rr]));
    }
    __syncthreads();

    // ---- forward: 3 radix-5 DIF stages (length-125 row FFTs) ----
    const float C72  =  0.30901699437494742f, S72  = 0.95105651629515357f;
    const float C144 = -0.80901699437494745f, S144 = 0.58778525229247314f;
#pragma unroll
    for (int sidx = 0; sidx < 3; sidx++) {
        const int L = (sidx == 0) ? 125 : (sidx == 1) ? 25 : 5;
        const int m = L / 5;
        const int f = 125 / L;
        for (int idx = tid; idx < 3200; idx += THREADS) {
            int r  = idx & 127;
            int bj = idx >> 7;
            int j  = bj % m;
            int base = r * 125 + (bj / m) * L + j;
            cplx a0 = S[base];
            cplx a1 = S[base + m];
            cplx a2 = S[base + 2 * m];
            cplx a3 = S[base + 3 * m];
            cplx a4 = S[base + 4 * m];
            cplx t1 = cadd(a1, a4), t3 = csub(a1, a4);
            cplx t2 = cadd(a2, a3), t4 = csub(a2, a3);
            cplx y0 = make_float2(a0.x + t1.x + t2.x, a0.y + t1.y + t2.y);
            cplx m1 = make_float2(a0.x + C72 * t1.x + C144 * t2.x,
                                  a0.y + C72 * t1.y + C144 * t2.y);
            cplx m2 = make_float2(a0.x + C144 * t1.x + C72 * t2.x,
                                  a0.y + C144 * t1.y + C72 * t2.y);
            cplx v1 = make_float2(S72 * t3.x + S144 * t4.x, S72 * t3.y + S144 * t4.y);
            cplx v2 = make_float2(S144 * t3.x - S72 * t4.x, S144 * t3.y - S72 * t4.y);
            // forward (e^-): y1=m1-i*v1, y2=m2-i*v2, y3=m2+i*v2, y4=m1+i*v1
            cplx y1 = make_float2(m1.x + v1.y, m1.y - v1.x);
            cplx y2 = make_float2(m2.x + v2.y, m2.y - v2.x);
            cplx y3 = make_float2(m2.x - v2.y, m2.y + v2.x);
            cplx y4 = make_float2(m1.x - v1.y, m1.y + v1.x);
            int jf = j * f;
            S[base]         = y0;
            S[base + m]     = cmul(y1, t125[jf]);
            S[base + 2 * m] = cmul(y2, t125[2 * jf]);
            S[base + 3 * m] = cmul(y3, t125[3 * jf]);
            S[base + 4 * m] = cmul(y4, t125[4 * jf]);
        }
        __syncthreads();
    }

    // ---- Hermitian split + pointwise multiply, in scrambled storage ----
    for (int k = tid; k <= 8000; k += THREADS) {
        if (k == 0) {
            cplx z = S[0];
            S[0] = make_float2(z.x * z.y, 0.0f);
        } else if (k == 8000) {
            const int addr = 64 * 125 + 62;
            cplx z = S[addr];
            S[addr] = make_float2(z.x * z.y, 0.0f);
        } else {
            int k1 = k & 127, k2 = k >> 7;
            int pa = k1 * 125 + dr5(k2);
            int kp = P_DIM - k;
            int k1p = kp & 127, k2p = kp >> 7;
            int pb = k1p * 125 + dr5(k2p);
            cplx A = S[pa];
            cplx Bv = S[pb];
            float F1r = 0.5f * (A.x + Bv.x), F1i = 0.5f * (A.y - Bv.y);
            float F2r = 0.5f * (A.y + Bv.y), F2i = 0.5f * (Bv.x - A.x);
            float Hr = F1r * F2r - F1i * F2i;
            float Hi = F1r * F2i + F1i * F2r;
            S[pa] = make_float2(Hr,  Hi);
            S[pb] = make_float2(Hr, -Hi);
        }
    }
    __syncthreads();

    // ---- inverse: 3 radix-5 DIT stages (rows), conj twiddles ----
#pragma unroll
    for (int sidx = 0; sidx < 3; sidx++) {
        const int L = (sidx == 0) ? 5 : (sidx == 1) ? 25 : 125;
        const int m = L / 5;
        const int f = 125 / L;
        for (int idx = tid; idx < 3200; idx += THREADS) {
            int r  = idx & 127;
            int bj = idx >> 7;
            int j  = bj % m;
            int base = r * 125 + (bj / m) * L + j;
            int jf = j * f;
            cplx a0 = S[base];
            cplx a1 = cmulc(S[base + m],     t125[jf]);
            cplx a2 = cmulc(S[base + 2 * m], t125[2 * jf]);
            cplx a3 = cmulc(S[base + 3 * m], t125[3 * jf]);
            cplx a4 = cmulc(S[base + 4 * m], t125[4 * jf]);
            cplx t1 = cadd(a1, a4), t3 = csub(a1, a4);
            cplx t2 = cadd(a2, a3), t4 = csub(a2, a3);
            cplx y0 = make_float2(a0.x + t1.x + t2.x, a0.y + t1.y + t2.y);
            cplx m1 = make_float2(a0.x + C72 * t1.x + C144 * t2.x,
                                  a0.y + C72 * t1.y + C144 * t2.y);
            cplx m2 = make_float2(a0.x + C144 * t1.x + C72 * t2.x,
                                  a0.y + C144 * t1.y + C72 * t2.y);
            cplx v1 = make_float2(S72 * t3.x + S144 * t4.x, S72 * t3.y + S144 * t4.y);
            cplx v2 = make_float2(S144 * t3.x - S72 * t4.x, S144 * t3.y - S72 * t4.y);
            // inverse (e^+): y1=m1+i*v1, y2=m2+i*v2, y3=m2-i*v2, y4=m1-i*v1
            S[base]         = y0;
            S[base + m]     = make_float2(m1.x - v1.y, m1.y + v1.x);
            S[base + 2 * m] = make_float2(m2.x - v2.y, m2.y + v2.x);
            S[base + 3 * m] = make_float2(m2.x + v2.y, m2.y - v2.x);
            S[base + 4 * m] = make_float2(m1.x + v1.y, m1.y - v1.x);
        }
        __syncthreads();
    }

    // ---- inverse inter-phase twiddle (conj) fused with radix-2 stage 6 ----
    for (int idx = tid; idx < 8000; idx += THREADS) {
        int c = idx % 125;
        int r = idx / 125;
        int p0 = r * 125 + c;
        int p1 = p0 + 8000;
        int mm = c * r;
        int q = mm / 125, rr = mm - q * 125;
        cplx u = cmulc(S[p0], cmul(t128[q], tS[rr]));
        int mm2 = mm + 64 * c;
        q = mm2 / 125; rr = mm2 - q * 125;
        cplx v = cmulc(S[p1], cmul(t128[q], tS[rr]));
        S[p0] = cadd(u, v);
        S[p1] = cmulc(csub(u, v), t128[r]);
    }
    __syncthreads();

    // ---- inverse radix-2 stages 5..3 merged ----
    for (int idx = tid; idx < 2000; idx += THREADS) {
        int c = idx % 125;
        int g = idx / 125;
        int u = g >> 3, j = g & 7;
        int base = (u * 64 + j) * 125 + c;
        cplx x[8];
#pragma unroll
        for (int t = 0; t < 8; t++) x[t] = S[base + t * 1000];
        radix8_dif(x, j, t128);
#pragma unroll
        for (int t = 0; t < 8; t++) S[base + t * 1000] = x[t];
    }
    __syncthreads();

    // ---- inverse radix-2 stages 2..0 merged, fused with output write ----
    // After this pass, element at row (8g+t), col c is time index
    // n = bitrev7(8g+t)*125 + c.  Write real part directly to gmem.
    const float scale = 1.0f / 16000.0f;
    for (int idx = tid; idx < 2000; idx += THREADS) {
        int c = idx % 125;
        int g = idx / 125;
        int base = g * 1000 + c;
        cplx x[8];
#pragma unroll
        for (int t = 0; t < 8; t++) x[t] = S[base + t * 125];
        radix8_dif(x, 0, t128);
#pragma unroll
        for (int t = 0; t < 8; t++) {
            int n1 = __brev(8 * g + t) >> 25;
            out[b * P_DIM + n1 * 125 + c] = x[t].x * scale;
        }
    }
}

extern "C" void kernel_launch(void* const* d_in, const int* in_sizes, int n_in,
                              void* d_out, int out_size) {
    const float* x1 = (const float*)d_in[0];
    const float* x2 = (const float*)d_in[1];
    const float* C1 = (const float*)d_in[2];
    const float* C2 = (const float*)d_in[3];
    float* out = (float*)d_out;

    extract_kernel<<<EX_BLOCKS, EX_THREADS>>>(C1, C2);

    const size_t smem = (size_t)P_DIM * sizeof(cplx);  // 128000 B
    cudaFuncSetAttribute(mcb_fft_kernel,
                         cudaFuncAttributeMaxDynamicSharedMemorySize, (int)smem);
    mcb_fft_kernel<<<B_BATCH, THREADS, smem>>>(x1, x2, out);
}

// round 5
// speedup vs baseline: 1.2762x; 1.0754x over previous
#include <cuda_runtime.h>
#include <math.h>

#define B_BATCH 128
#define D_DIM   2048
#define P_DIM   16000
#define THREADS 1024

static __device__ int   g_idx[2 * D_DIM];
static __device__ float g_sgn[2 * D_DIM];

// ---------------------------------------------------------------------------
// Kernel 1: recover the sparse count-sketch (one +/-1 per row) from dense C.
// Branch-free moment reduction: sgn = sum(C[row,:]), idx = sgn * sum(p*C[row,p]).
// Exact in fp32 (idx < 2^14, every other term is a literal 0).  One block per
// row -> pure streaming FMA, perfectly coalesced, max MLP.
// ---------------------------------------------------------------------------
#define EX_THREADS 256

__global__ void __launch_bounds__(EX_THREADS)
extract_kernel(const float* __restrict__ C1, const float* __restrict__ C2) {
    const int row = blockIdx.x;  // 0..4095
    const float4* b4 = (const float4*)((row < D_DIM)
                        ? (C1 + (size_t)row * P_DIM)
                        : (C2 + (size_t)(row - D_DIM) * P_DIM));
    float s = 0.0f, w = 0.0f;
#pragma unroll 4
    for (int i = threadIdx.x; i < P_DIM / 4; i += EX_THREADS) {
        float4 v = b4[i];
        float p0 = (float)(4 * i);
        s += (v.x + v.y) + (v.z + v.w);
        w += p0 * v.x + (p0 + 1.0f) * v.y + (p0 + 2.0f) * v.z + (p0 + 3.0f) * v.w;
    }
    // warp reduce
#pragma unroll
    for (int o = 16; o > 0; o >>= 1) {
        s += __shfl_down_sync(0xFFFFFFFFu, s, o);
        w += __shfl_down_sync(0xFFFFFFFFu, w, o);
    }
    __shared__ float ss[EX_THREADS / 32], sw[EX_THREADS / 32];
    int lane = threadIdx.x & 31, warp = threadIdx.x >> 5;
    if (lane == 0) { ss[warp] = s; sw[warp] = w; }
    __syncthreads();
    if (warp == 0) {
        s = (lane < EX_THREADS / 32) ? ss[lane] : 0.0f;
        w = (lane < EX_THREADS / 32) ? sw[lane] : 0.0f;
#pragma unroll
        for (int o = 4; o > 0; o >>= 1) {
            s += __shfl_down_sync(0xFFFFFFFFu, s, o);
            w += __shfl_down_sync(0xFFFFFFFFu, w, o);
        }
        if (lane == 0) {
            g_sgn[row] = s;
            g_idx[row] = (int)rintf(w * s);
        }
    }
}

// base-5 digit reversal of 3 digits (involution), x in [0,125)
__device__ __forceinline__ int dr5(int x) {
    int a = x / 25;
    int rem = x - 25 * a;
    int b = rem / 5;
    int c = rem - 5 * b;
    return c * 25 + b * 5 + a;
}

typedef float2 cplx;
__device__ __forceinline__ cplx cmul(cplx a, cplx b) {
    return make_float2(a.x * b.x - a.y * b.y, a.x * b.y + a.y * b.x);
}
__device__ __forceinline__ cplx cmulc(cplx a, cplx b) {   // a * conj(b)
    return make_float2(a.x * b.x + a.y * b.y, a.y * b.x - a.x * b.y);
}
__device__ __forceinline__ cplx cadd(cplx a, cplx b) { return make_float2(a.x + b.x, a.y + b.y); }
__device__ __forceinline__ cplx csub(cplx a, cplx b) { return make_float2(a.x - b.x, a.y - b.y); }

// Radix-8 DIT (3 merged radix-2 DIT stages).
__device__ __forceinline__ void radix8_dit(cplx x[8], int j, const cplx* t128) {
    cplx wa = t128[8 * j];
#pragma unroll
    for (int t = 0; t < 8; t += 2) {
        cplx v = cmul(x[t + 1], wa);
        x[t + 1] = csub(x[t], v);
        x[t]     = cadd(x[t], v);
    }
    cplx wb0 = t128[4 * j];
    cplx wb1 = t128[4 * j + 32];
#pragma unroll
    for (int q = 0; q < 2; q++) {
        int b0 = 4 * q;
        {
            cplx v = cmul(x[b0 + 2], wb0);
            x[b0 + 2] = csub(x[b0], v);
            x[b0]     = cadd(x[b0], v);
        }
        {
            cplx v = cmul(x[b0 + 3], wb1);
            x[b0 + 3] = csub(x[b0 + 1], v);
            x[b0 + 1] = cadd(x[b0 + 1], v);
        }
    }
#pragma unroll
    for (int t = 0; t < 4; t++) {
        cplx w = t128[2 * j + 16 * t];
        cplx v = cmul(x[t + 4], w);
        x[t + 4] = csub(x[t], v);
        x[t]     = cadd(x[t], v);
    }
}

// Radix-8 DIF (3 merged radix-2 DIF stages, inverse direction = conj twiddles).
__device__ __forceinline__ void radix8_dif(cplx x[8], int j, const cplx* t128) {
#pragma unroll
    for (int t = 0; t < 4; t++) {
        cplx w = t128[2 * j + 16 * t];
        cplx u = x[t], v = x[t + 4];
        x[t]     = cadd(u, v);
        x[t + 4] = cmulc(csub(u, v), w);
    }
    cplx wb0 = t128[4 * j];
    cplx wb1 = t128[4 * j + 32];
#pragma unroll
    for (int q = 0; q < 2; q++) {
        int b0 = 4 * q;
        {
            cplx u = x[b0], v = x[b0 + 2];
            x[b0]     = cadd(u, v);
            x[b0 + 2] = cmulc(csub(u, v), wb0);
        }
        {
            cplx u = x[b0 + 1], v = x[b0 + 3];
            x[b0 + 1] = cadd(u, v);
            x[b0 + 3] = cmulc(csub(u, v), wb1);
        }
    }
    cplx wa = t128[8 * j];
#pragma unroll
    for (int t = 0; t < 8; t += 2) {
        cplx u = x[t], v = x[t + 1];
        x[t]     = cadd(u, v);
        x[t + 1] = cmulc(csub(u, v), wa);
    }
}

// ---------------------------------------------------------------------------
// Kernel 2: z = y1 + i*y2, Z = FFT_16000 (128x125 four-step), Hermitian split
// + pointwise multiply, phi = Re(IFFT)/N.  float2 interleaved shared storage.
// ---------------------------------------------------------------------------
__global__ void __launch_bounds__(THREADS)
mcb_fft_kernel(const float* __restrict__ x1, const float* __restrict__ x2,
               float* __restrict__ out) {
    extern __shared__ cplx S[];                // 16000 complex = 128000 B
    __shared__ cplx t128[128];                 // e^{-2pi i t/128}
    __shared__ cplx t125[125];                 // e^{-2pi i t/125}
    __shared__ cplx tS[125];                   // e^{-2pi i t/16000}

    const int tid = threadIdx.x;
    const int b   = blockIdx.x;
    const double TWO_PI = 6.283185307179586476925286766559;

    for (int t = tid; t < 128; t += THREADS) {
        double s, c; sincos(-TWO_PI * (double)t / 128.0, &s, &c);
        t128[t] = make_float2((float)c, (float)s);
    }
    for (int t = tid; t < 125; t += THREADS) {
        double s, c;
        sincos(-TWO_PI * (double)t / 125.0, &s, &c);
        t125[t] = make_float2((float)c, (float)s);
        sincos(-TWO_PI * (double)t / 16000.0, &s, &c);
        tS[t] = make_float2((float)c, (float)s);
    }
    for (int i = tid; i < P_DIM; i += THREADS) S[i] = make_float2(0.0f, 0.0f);
    __syncthreads();

    // scatter: y1 -> real, y2 -> imag, rows bit-reversed for the DIT stages
    for (int d = tid; d < D_DIM; d += THREADS) {
        int p = g_idx[d];
        float v = x1[b * D_DIM + d] * g_sgn[d];
        int n1 = p / 125, n2 = p - n1 * 125;
        int r = __brev(n1) >> 25;
        atomicAdd(&S[r * 125 + n2].x, v);
        p = g_idx[D_DIM + d];
        v = x2[b * D_DIM + d] * g_sgn[D_DIM + d];
        n1 = p / 125; n2 = p - n1 * 125;
        r = __brev(n1) >> 25;
        atomicAdd(&S[r * 125 + n2].y, v);
    }
    __syncthreads();

    // ---- forward radix-2 stages 0..2 merged (rows 8g+t, fixed col) ----
    for (int idx = tid; idx < 2000; idx += THREADS) {
        int c = idx % 125;
        int g = idx / 125;
        int base = g * 1000 + c;
        cplx x[8];
#pragma unroll
        for (int t = 0; t < 8; t++) x[t] = S[base + t * 125];
        radix8_dit(x, 0, t128);
#pragma unroll
        for (int t = 0; t < 8; t++) S[base + t * 125] = x[t];
    }
    __syncthreads();

    // ---- forward radix-2 stages 3..5 merged (rows 64u + j + 8t) ----
    for (int idx = tid; idx < 2000; idx += THREADS) {
        int c = idx % 125;
        int g = idx / 125;          // 0..15
        int u = g >> 3, j = g & 7;
        int base = (u * 64 + j) * 125 + c;
        cplx x[8];
#pragma unroll
        for (int t = 0; t < 8; t++) x[t] = S[base + t * 1000];
        radix8_dit(x, j, t128);
#pragma unroll
        for (int t = 0; t < 8; t++) S[base + t * 1000] = x[t];
    }
    __syncthreads();

    // ---- forward stage 6 (radix-2) fused with inter-phase twiddle ----
    for (int idx = tid; idx < 8000; idx += THREADS) {
        int c = idx % 125;
        int r = idx / 125;          // 0..63
        int p0 = r * 125 + c;
        int p1 = p0 + 8000;
        cplx u = S[p0];
        cplx v = cmul(S[p1], t128[r]);
        cplx X0 = cadd(u, v);
        cplx X1 = csub(u, v);
        int mm = c * r;
        int q = mm / 125, rr = mm - q * 125;
        S[p0] = cmul(X0, cmul(t128[q], tS[rr]));
        int mm2 = mm + 64 * c;
        q = mm2 / 125; rr = mm2 - q * 125;
        S[p1] = cmul(X1, cmul(t128[q], tS[rr]));
    }
    __syncthreads();

    // ---- forward: 3 radix-5 DIF stages (length-125 row FFTs) ----
    const float C72  =  0.30901699437494742f, S72  = 0.95105651629515357f;
    const float C144 = -0.80901699437494745f, S144 = 0.58778525229247314f;
#pragma unroll
    for (int sidx = 0; sidx < 3; sidx++) {
        const int L = (sidx == 0) ? 125 : (sidx == 1) ? 25 : 5;
        const int m = L / 5;
        const int f = 125 / L;
        for (int idx = tid; idx < 3200; idx += THREADS) {
            int r  = idx & 127;
            int bj = idx >> 7;
            int j  = bj % m;
            int base = r * 125 + (bj / m) * L + j;
            cplx a0 = S[base];
            cplx a1 = S[base + m];
            cplx a2 = S[base + 2 * m];
            cplx a3 = S[base + 3 * m];
            cplx a4 = S[base + 4 * m];
            cplx t1 = cadd(a1, a4), t3 = csub(a1, a4);
            cplx t2 = cadd(a2, a3), t4 = csub(a2, a3);
            cplx y0 = make_float2(a0.x + t1.x + t2.x, a0.y + t1.y + t2.y);
            cplx m1 = make_float2(a0.x + C72 * t1.x + C144 * t2.x,
                                  a0.y + C72 * t1.y + C144 * t2.y);
            cplx m2 = make_float2(a0.x + C144 * t1.x + C72 * t2.x,
                                  a0.y + C144 * t1.y + C72 * t2.y);
            cplx v1 = make_float2(S72 * t3.x + S144 * t4.x, S72 * t3.y + S144 * t4.y);
            cplx v2 = make_float2(S144 * t3.x - S72 * t4.x, S144 * t3.y - S72 * t4.y);
            // forward (e^-): y1=m1-i*v1, y2=m2-i*v2, y3=m2+i*v2, y4=m1+i*v1
            cplx y1 = make_float2(m1.x + v1.y, m1.y - v1.x);
            cplx y2 = make_float2(m2.x + v2.y, m2.y - v2.x);
            cplx y3 = make_float2(m2.x - v2.y, m2.y + v2.x);
            cplx y4 = make_float2(m1.x - v1.y, m1.y + v1.x);
            int jf = j * f;
            S[base]         = y0;
            S[base + m]     = cmul(y1, t125[jf]);
            S[base + 2 * m] = cmul(y2, t125[2 * jf]);
            S[base + 3 * m] = cmul(y3, t125[3 * jf]);
            S[base + 4 * m] = cmul(y4, t125[4 * jf]);
        }
        __syncthreads();
    }

    // ---- Hermitian split + pointwise multiply, in scrambled storage ----
    for (int k = tid; k <= 8000; k += THREADS) {
        if (k == 0) {
            cplx z = S[0];
            S[0] = make_float2(z.x * z.y, 0.0f);
        } else if (k == 8000) {
            const int addr = 64 * 125 + 62;
            cplx z = S[addr];
            S[addr] = make_float2(z.x * z.y, 0.0f);
        } else {
            int k1 = k & 127, k2 = k >> 7;
            int pa = k1 * 125 + dr5(k2);
            int kp = P_DIM - k;
            int k1p = kp & 127, k2p = kp >> 7;
            int pb = k1p * 125 + dr5(k2p);
            cplx A = S[pa];
            cplx Bv = S[pb];
            float F1r = 0.5f * (A.x + Bv.x), F1i = 0.5f * (A.y - Bv.y);
            float F2r = 0.5f * (A.y + Bv.y), F2i = 0.5f * (Bv.x - A.x);
            float Hr = F1r * F2r - F1i * F2i;
            float Hi = F1r * F2i + F1i * F2r;
            S[pa] = make_float2(Hr,  Hi);
            S[pb] = make_float2(Hr, -Hi);
        }
    }
    __syncthreads();

    // ---- inverse: 3 radix-5 DIT stages (rows), conj twiddles ----
#pragma unroll
    for (int sidx = 0; sidx < 3; sidx++) {
        const int L = (sidx == 0) ? 5 : (sidx == 1) ? 25 : 125;
        const int m = L / 5;
        const int f = 125 / L;
        for (int idx = tid; idx < 3200; idx += THREADS) {
            int r  = idx & 127;
            int bj = idx >> 7;
            int j  = bj % m;
            int base = r * 125 + (bj / m) * L + j;
            int jf = j * f;
            cplx a0 = S[base];
            cplx a1 = cmulc(S[base + m],     t125[jf]);
            cplx a2 = cmulc(S[base + 2 * m], t125[2 * jf]);
            cplx a3 = cmulc(S[base + 3 * m], t125[3 * jf]);
            cplx a4 = cmulc(S[base + 4 * m], t125[4 * jf]);
            cplx t1 = cadd(a1, a4), t3 = csub(a1, a4);
            cplx t2 = cadd(a2, a3), t4 = csub(a2, a3);
            cplx y0 = make_float2(a0.x + t1.x + t2.x, a0.y + t1.y + t2.y);
            cplx m1 = make_float2(a0.x + C72 * t1.x + C144 * t2.x,
                                  a0.y + C72 * t1.y + C144 * t2.y);
            cplx m2 = make_float2(a0.x + C144 * t1.x + C72 * t2.x,
                                  a0.y + C144 * t1.y + C72 * t2.y);
            cplx v1 = make_float2(S72 * t3.x + S144 * t4.x, S72 * t3.y + S144 * t4.y);
            cplx v2 = make_float2(S144 * t3.x - S72 * t4.x, S144 * t3.y - S72 * t4.y);
            // inverse (e^+): y1=m1+i*v1, y2=m2+i*v2, y3=m2-i*v2, y4=m1-i*v1
            S[base]         = y0;
            S[base + m]     = make_float2(m1.x - v1.y, m1.y + v1.x);
            S[base + 2 * m] = make_float2(m2.x - v2.y, m2.y + v2.x);
            S[base + 3 * m] = make_float2(m2.x + v2.y, m2.y - v2.x);
            S[base + 4 * m] = make_float2(m1.x + v1.y, m1.y - v1.x);
        }
        __syncthreads();
    }

    // ---- inverse inter-phase twiddle (conj) fused with radix-2 stage 6 ----
    for (int idx = tid; idx < 8000; idx += THREADS) {
        int c = idx % 125;
        int r = idx / 125;
        int p0 = r * 125 + c;
        int p1 = p0 + 8000;
        int mm = c * r;
        int q = mm / 125, rr = mm - q * 125;
        cplx u = cmulc(S[p0], cmul(t128[q], tS[rr]));
        int mm2 = mm + 64 * c;
        q = mm2 / 125; rr = mm2 - q * 125;
        cplx v = cmulc(S[p1], cmul(t128[q], tS[rr]));
        S[p0] = cadd(u, v);
        S[p1] = cmulc(csub(u, v), t128[r]);
    }
    __syncthreads();

    // ---- inverse radix-2 stages 5..3 merged ----
    for (int idx = tid; idx < 2000; idx += THREADS) {
        int c = idx % 125;
        int g = idx / 125;
        int u = g >> 3, j = g & 7;
        int base = (u * 64 + j) * 125 + c;
        cplx x[8];
#pragma unroll
        for (int t = 0; t < 8; t++) x[t] = S[base + t * 1000];
        radix8_dif(x, j, t128);
#pragma unroll
        for (int t = 0; t < 8; t++) S[base + t * 1000] = x[t];
    }
    __syncthreads();

    // ---- inverse radix-2 stages 2..0 merged, fused with output write ----
    const float scale = 1.0f / 16000.0f;
    for (int idx = tid; idx < 2000; idx += THREADS) {
        int c = idx % 125;
        int g = idx / 125;
        int base = g * 1000 + c;
        cplx x[8];
#pragma unroll
        for (int t = 0; t < 8; t++) x[t] = S[base + t * 125];
        radix8_dif(x, 0, t128);
#pragma unroll
        for (int t = 0; t < 8; t++) {
            int n1 = __brev(8 * g + t) >> 25;
            out[b * P_DIM + n1 * 125 + c] = x[t].x * scale;
        }
    }
}

extern "C" void kernel_launch(void* const* d_in, const int* in_sizes, int n_in,
                              void* d_out, int out_size) {
    const float* x1 = (const float*)d_in[0];
    const float* x2 = (const float*)d_in[1];
    const float* C1 = (const float*)d_in[2];
    const float* C2 = (const float*)d_in[3];
    float* out = (float*)d_out;

    extract_kernel<<<2 * D_DIM, EX_THREADS>>>(C1, C2);

    const size_t smem = (size_t)P_DIM * sizeof(cplx);  // 128000 B
    cudaFuncSetAttribute(mcb_fft_kernel,
                         cudaFuncAttributeMaxDynamicSharedMemorySize, (int)smem);
    mcb_fft_kernel<<<B_BATCH, THREADS, smem>>>(x1, x2, out);
}